// round 5
// baseline (speedup 1.0000x reference)
#include <cuda_runtime.h>

typedef unsigned long long ull;

// ---- packed f32x2 helpers ----
__device__ __forceinline__ ull pk2(float lo, float hi) {
    ull r; asm("mov.b64 %0, {%1, %2};" : "=l"(r) : "f"(lo), "f"(hi)); return r;
}
__device__ __forceinline__ ull bc2(float v) { return pk2(v, v); }
__device__ __forceinline__ void upk2(ull r, float& lo, float& hi) {
    asm("mov.b64 {%0, %1}, %2;" : "=f"(lo), "=f"(hi) : "l"(r));
}
__device__ __forceinline__ ull fma2(ull a, ull b, ull c) {
    ull d; asm("fma.rn.f32x2 %0, %1, %2, %3;" : "=l"(d) : "l"(a), "l"(b), "l"(c)); return d;
}
__device__ __forceinline__ ull add2(ull a, ull b) {
    ull d; asm("add.rn.f32x2 %0, %1, %2;" : "=l"(d) : "l"(a), "l"(b)); return d;
}
__device__ __forceinline__ ull mul2(ull a, ull b) {
    ull d; asm("mul.rn.f32x2 %0, %1, %2;" : "=l"(d) : "l"(a), "l"(b)); return d;
}
__device__ __forceinline__ float ex2a(float x) {
    float y; asm("ex2.approx.f32 %0, %1;" : "=f"(y) : "f"(x)); return y;
}
__device__ __forceinline__ float rcpa(float x) {
    float y; asm("rcp.approx.f32 %0, %1;" : "=f"(y) : "f"(x)); return y;
}

// Shapes: b=4, c=16, m=8, h=w=64, O=64.
// Block: 1024 threads, tile = 2 rows x 8 cols.
// Thread: jq = t&3 (j quarter), sp = (t>>2)&3 (superpixel), o = t>>4.
// Smem (floats):
//   qs  [0,16448)      q[i][o*16+pix], i-stride 1028
//   xs  [16448,18560)  x[ch][m*16+pix], ch-stride 132
//   res [18560,18816)  0.125*sum_m x, [i*16+pix]
//   wqs [18816,19328)  wq * 0.125*log2(e), [o*8+m]
//   wkp [19328,19904)  ull row-pairs [r2*9+m], rows (2r2, 2r2+1)
//   wvp [19904,20480)  same for wv
#define QS_I 1028
#define XS_CH 132
#define SMEM_FLOATS 20480
#define SMEM_BYTES (SMEM_FLOATS * 4)

__global__ __launch_bounds__(1024, 1) void adapt_attn(
    const float* __restrict__ x,
    const float* __restrict__ wq,
    const float* __restrict__ wk,
    const float* __restrict__ wv,
    float* __restrict__ out)
{
    extern __shared__ __align__(16) float smem[];
    float* qs  = smem;
    float* xs  = smem + 16448;
    float* res = smem + 18560;
    float* wqs = smem + 18816;
    ull*   wkp = (ull*)(smem + 19328);
    ull*   wvp = (ull*)(smem + 19904);

    const int t   = threadIdx.x;
    const int lwg = blockIdx.x;   // 0..7
    const int lh  = blockIdx.y;   // 0..31
    const int b   = blockIdx.z;   // 0..3
    const int hh0 = 2 * lh, ww0 = 8 * lwg;

    // ---- stage x tile (t<512): pix = sp*4 + row*2 + col ----
    if (t < 512) {
        int q4  = t & 1;
        int hhi = (t >> 1) & 1;
        int m   = (t >> 2) & 7;
        int ch  = t >> 5;
        const float4 v = *reinterpret_cast<const float4*>(
            x + ((b * 16 + ch) * 8 + m) * 4096 + (hh0 + hhi) * 64 + ww0 + 4 * q4);
        float* dst = xs + ch * XS_CH + m * 16 + 8 * q4 + 2 * hhi;
        *reinterpret_cast<ull*>(dst)     = pk2(v.x, v.y);
        *reinterpret_cast<ull*>(dst + 4) = pk2(v.z, v.w);
        wqs[t] = wq[t] * 0.18033688011112042f;   // 0.125 * log2(e)
    } else {
        int u  = t & 255;
        int m  = u & 7;
        int r2 = u >> 3;                          // 0..31 -> rows (2r2, 2r2+1)
        if (t < 768)
            wkp[r2 * 9 + m] = pk2(wk[(2 * r2) * 8 + m], wk[(2 * r2 + 1) * 8 + m]);
        else
            wvp[r2 * 9 + m] = pk2(wv[(2 * r2) * 8 + m], wv[(2 * r2 + 1) * 8 + m]);
    }
    __syncthreads();

    // ---- cooperative q: thread (i = t&15, o = t>>4) computes 16 pixels ----
    {
        int i = t & 15, oo = t >> 4;
        const float* xr = xs + i * XS_CH;
        ull acc[8];
#pragma unroll
        for (int p = 0; p < 8; ++p) acc[p] = 0ull;
#pragma unroll
        for (int m = 0; m < 8; ++m) {
            ull wrb = bc2(wqs[oo * 8 + m]);
            const ull* r = reinterpret_cast<const ull*>(xr + m * 16);
#pragma unroll
            for (int p = 0; p < 8; ++p) acc[p] = fma2(wrb, r[p], acc[p]);
        }
        ull* qdst = reinterpret_cast<ull*>(qs + i * QS_I + oo * 16);
#pragma unroll
        for (int p = 0; p < 8; ++p) qdst[p] = acc[p];
    }
    // ---- res = 0.125 * sum_m x ----
    if (t < 256) {
        int i = t >> 4, pix = t & 15;
        const float* xr = xs + i * XS_CH + pix;
        float s = 0.f;
#pragma unroll
        for (int m = 0; m < 8; ++m) s += xr[m * 16];
        res[i * 16 + pix] = 0.125f * s;
    }

    // ---- per-thread k/v for its (o, jq) quarter: 4 j as 2 pairs ----
    const int jq = t & 3;
    const int sp = (t >> 2) & 3;
    const int o  = t >> 4;
    const int ck = o >> 2;

    ull kq[2][4], vq[2][4];          // [j2][p], packed over j-pairs
#pragma unroll
    for (int j2 = 0; j2 < 2; ++j2)
#pragma unroll
        for (int p = 0; p < 4; ++p) { kq[j2][p] = 0ull; vq[j2][p] = 0ull; }
    {
        const int r2b = (o & 3) * 8 + jq * 2;       // row-pair base
        const float* xck = xs + ck * XS_CH;
        const ull* wkg = wkp + r2b * 9;
        const ull* wvg = wvp + r2b * 9;
#pragma unroll
        for (int m = 0; m < 8; ++m) {
            float4 xv = *reinterpret_cast<const float4*>(xck + m * 16 + sp * 4);
            ull xb0 = bc2(xv.x), xb1 = bc2(xv.y), xb2 = bc2(xv.z), xb3 = bc2(xv.w);
#pragma unroll
            for (int j2 = 0; j2 < 2; ++j2) {
                ull wkv = wkg[j2 * 9 + m];
                kq[j2][0] = fma2(wkv, xb0, kq[j2][0]);
                kq[j2][1] = fma2(wkv, xb1, kq[j2][1]);
                kq[j2][2] = fma2(wkv, xb2, kq[j2][2]);
                kq[j2][3] = fma2(wkv, xb3, kq[j2][3]);
                ull wvv = wvg[j2 * 9 + m];
                vq[j2][0] = fma2(wvv, xb0, vq[j2][0]);
                vq[j2][1] = fma2(wvv, xb1, vq[j2][1]);
                vq[j2][2] = fma2(wvv, xb2, vq[j2][2]);
                vq[j2][3] = fma2(wvv, xb3, vq[j2][3]);
            }
        }
    }
    __syncthreads();

    const int rsel = jq >> 1;                        // which row this lane stores
    const bool do_store = (jq & 1) == 0;
    const float* qso  = qs + o * 16 + sp * 4;
    const ull*   resp = reinterpret_cast<const ull*>(res) + sp * 2 + rsel;
    float* op = out + ((b * 16) * 64 + o) * 4096 + (hh0 + rsel) * 64 + ww0 + 2 * sp;

#pragma unroll 1
    for (int i = 0; i < 16; ++i) {
        float4 qv = *reinterpret_cast<const float4*>(qso + i * QS_I);
        ull qb0 = bc2(qv.x), qb1 = bc2(qv.y), qb2 = bc2(qv.z), qb3 = bc2(qv.w);

        // att -> e = 2^att (scaling folded into wq; no max needed: |att| << 30)
        ull ep[2];
#pragma unroll
        for (int j2 = 0; j2 < 2; ++j2) {
            ull at = mul2(qb0, kq[j2][0]);
            at = fma2(qb1, kq[j2][1], at);
            at = fma2(qb2, kq[j2][2], at);
            at = fma2(qb3, kq[j2][3], at);
            float alo, ahi; upk2(at, alo, ahi);
            ep[j2] = pk2(ex2a(alo), ex2a(ahi));
        }

        // softmax denominator: local 4 exps + butterfly over 4 jq lanes
        float slo, shi; upk2(add2(ep[0], ep[1]), slo, shi);
        float fs = slo + shi;
        fs += __shfl_xor_sync(0xffffffffu, fs, 1);
        fs += __shfl_xor_sync(0xffffffffu, fs, 2);
        float inv = rcpa(fs);

        // output partial over this thread's 4 j
        ull oa0 = mul2(ep[0], vq[0][0]);
        ull oa1 = mul2(ep[0], vq[0][1]);
        ull oa2 = mul2(ep[0], vq[0][2]);
        ull oa3 = mul2(ep[0], vq[0][3]);
        oa0 = fma2(ep[1], vq[1][0], oa0);
        oa1 = fma2(ep[1], vq[1][1], oa1);
        oa2 = fma2(ep[1], vq[1][2], oa2);
        oa3 = fma2(ep[1], vq[1][3], oa3);
        float f0, f1, f2, f3, g0, g1, g2, g3;
        upk2(oa0, f0, g0); upk2(oa1, f1, g1);
        upk2(oa2, f2, g2); upk2(oa3, f3, g3);
        ull mineA = pk2(f0 + g0, f1 + g1);   // row hh0   pixels (c0,c1)
        ull mineB = pk2(f2 + g2, f3 + g3);   // row hh0+1 pixels (c0,c1)

        // stage 1 (xor 2): lanes jq&2==0 gather row A, jq&2!=0 gather row B
        ull keep = (jq & 2) ? mineB : mineA;
        ull send = (jq & 2) ? mineA : mineB;
        ull half = add2(keep, __shfl_xor_sync(0xffffffffu, send, 2));
        // stage 2 (xor 1): combine the two j-halves of the same row
        ull full = add2(half, __shfl_xor_sync(0xffffffffu, half, 1));

        if (do_store) {
            ull fin = fma2(full, bc2(inv), resp[i * 8]);
            *reinterpret_cast<ull*>(op) = fin;
        }
        op += 64 * 4096;
    }
}

extern "C" void kernel_launch(void* const* d_in, const int* in_sizes, int n_in,
                              void* d_out, int out_size) {
    const float* x  = (const float*)d_in[0];
    const float* wq = (const float*)d_in[1];
    const float* wk = (const float*)d_in[2];
    const float* wv = (const float*)d_in[3];
    // d_in[4] (w_p): positional term is constant over the softmax axis -> cancels exactly.
    static int attr_set = 0;
    if (!attr_set) {
        cudaFuncSetAttribute(adapt_attn, cudaFuncAttributeMaxDynamicSharedMemorySize,
                             SMEM_BYTES);
        attr_set = 1;
    }
    dim3 grid(8, 32, 4);
    adapt_attn<<<grid, 1024, SMEM_BYTES>>>(x, wq, wk, wv, (float*)d_out);
}

// round 6
// speedup vs baseline: 1.1863x; 1.1863x over previous
#include <cuda_runtime.h>

typedef unsigned long long ull;

// ---- packed f32x2 helpers ----
__device__ __forceinline__ ull pk2(float lo, float hi) {
    ull r; asm("mov.b64 %0, {%1, %2};" : "=l"(r) : "f"(lo), "f"(hi)); return r;
}
__device__ __forceinline__ ull bc2(float v) { return pk2(v, v); }
__device__ __forceinline__ void upk2(ull r, float& lo, float& hi) {
    asm("mov.b64 {%0, %1}, %2;" : "=f"(lo), "=f"(hi) : "l"(r));
}
__device__ __forceinline__ ull fma2(ull a, ull b, ull c) {
    ull d; asm("fma.rn.f32x2 %0, %1, %2, %3;" : "=l"(d) : "l"(a), "l"(b), "l"(c)); return d;
}
__device__ __forceinline__ ull add2(ull a, ull b) {
    ull d; asm("add.rn.f32x2 %0, %1, %2;" : "=l"(d) : "l"(a), "l"(b)); return d;
}
__device__ __forceinline__ ull mul2(ull a, ull b) {
    ull d; asm("mul.rn.f32x2 %0, %1, %2;" : "=l"(d) : "l"(a), "l"(b)); return d;
}
__device__ __forceinline__ float ex2a(float x) {
    float y; asm("ex2.approx.f32 %0, %1;" : "=f"(y) : "f"(x)); return y;
}
__device__ __forceinline__ float rcpa(float x) {
    float y; asm("rcp.approx.f32 %0, %1;" : "=f"(y) : "f"(x)); return y;
}

// Shapes: b=4, c=16, m=8, h=w=64, O=64.
// Block: 256 threads, tile = 2 rows x 8 cols (4 superpixels).
// Thread: sp = t&3, o = t>>2. Full j=16 per thread; no shuffles.
// Smem (floats):
//   qs  [0,16448)      q[i][o*16+pix] (pre-scaled by 0.125*log2e), i-stride 1028
//   xs  [16448,18560)  x[ch][m*16+pix], ch-stride 132
//   res [18560,18816)  0.125*sum_m x, [i*16+pix]
//   wqs [18816,19328)  wq * 0.125*log2(e), [o*8+m]
//   wkp [19328,19904)  ull j-pairs [r2*9+m], rows (2r2, 2r2+1)
//   wvp [19904,20480)  same for wv
#define QS_I 1028
#define XS_CH 132
#define SMEM_FLOATS 20480
#define SMEM_BYTES (SMEM_FLOATS * 4)

__global__ __launch_bounds__(256, 1) void adapt_attn(
    const float* __restrict__ x,
    const float* __restrict__ wq,
    const float* __restrict__ wk,
    const float* __restrict__ wv,
    float* __restrict__ out)
{
    extern __shared__ __align__(16) float smem[];
    float* qs  = smem;
    float* xs  = smem + 16448;
    float* res = smem + 18560;
    float* wqs = smem + 18816;
    ull*   wkp = (ull*)(smem + 19328);
    ull*   wvp = (ull*)(smem + 19904);

    const int t   = threadIdx.x;
    const int lwg = blockIdx.x;   // 0..7
    const int lh  = blockIdx.y;   // 0..31
    const int b   = blockIdx.z;   // 0..3
    const int hh0 = 2 * lh, ww0 = 8 * lwg;

    // ---- stage x tile (512 float4): pix = sp*4 + (hhi*2 + colbit) ----
#pragma unroll
    for (int it = 0; it < 2; ++it) {
        int idx = t + it * 256;
        int q4  = idx & 1;
        int hhi = (idx >> 1) & 1;
        int m   = (idx >> 2) & 7;
        int ch  = idx >> 5;
        const float4 v = *reinterpret_cast<const float4*>(
            x + ((b * 16 + ch) * 8 + m) * 4096 + (hh0 + hhi) * 64 + ww0 + 4 * q4);
        float* dst = xs + ch * XS_CH + m * 16 + 8 * q4 + 2 * hhi;
        *reinterpret_cast<ull*>(dst)     = pk2(v.x, v.y);
        *reinterpret_cast<ull*>(dst + 4) = pk2(v.z, v.w);
    }
    // ---- stage weights ----
    wqs[t]       = wq[t]       * 0.18033688011112042f;  // 0.125 * log2(e)
    wqs[t + 256] = wq[t + 256] * 0.18033688011112042f;
    {
        int m = t & 7, r2 = t >> 3;                      // rows (2r2, 2r2+1)
        wkp[r2 * 9 + m] = pk2(wk[(2 * r2) * 8 + m], wk[(2 * r2 + 1) * 8 + m]);
        wvp[r2 * 9 + m] = pk2(wv[(2 * r2) * 8 + m], wv[(2 * r2 + 1) * 8 + m]);
    }
    __syncthreads();

    // ---- res = 0.125 * sum_m x ----
    {
        int i = t >> 4, pix = t & 15;
        const float* xr = xs + i * XS_CH + pix;
        float s = 0.f;
#pragma unroll
        for (int m = 0; m < 8; ++m) s += xr[m * 16];
        res[i * 16 + pix] = 0.125f * s;
    }

    // ---- cooperative q: thread (i = t&15, og = t>>4) -> 4 o values ----
    {
        int i = t & 15, og = t >> 4;
        const ull* xr = reinterpret_cast<const ull*>(xs + i * XS_CH);
#pragma unroll
        for (int n = 0; n < 4; ++n) {
            int o = og * 4 + n;
            ull acc[8];
#pragma unroll
            for (int p = 0; p < 8; ++p) acc[p] = 0ull;
#pragma unroll
            for (int m = 0; m < 8; ++m) {
                ull wb = bc2(wqs[o * 8 + m]);
#pragma unroll
                for (int p = 0; p < 8; ++p)
                    acc[p] = fma2(wb, xr[m * 8 + p], acc[p]);
            }
            ull* qd = reinterpret_cast<ull*>(qs + i * QS_I + o * 16);
#pragma unroll
            for (int p = 0; p < 8; ++p) qd[p] = acc[p];
        }
    }

    // ---- per-thread k/v (full j = 16, packed over j-pairs) ----
    const int sp = t & 3;
    const int o  = t >> 2;
    const int ck = o >> 2;

    ull kq[8][4], vq[8][4];          // [j2][p], lo = even j, hi = odd j
#pragma unroll
    for (int j2 = 0; j2 < 8; ++j2)
#pragma unroll
        for (int p = 0; p < 4; ++p) { kq[j2][p] = 0ull; vq[j2][p] = 0ull; }
    {
        const ull* wkg = wkp + ((o & 3) * 8) * 9;
        const ull* wvg = wvp + ((o & 3) * 8) * 9;
        const float* xck = xs + ck * XS_CH;
#pragma unroll
        for (int m = 0; m < 8; ++m) {
            float4 xv = *reinterpret_cast<const float4*>(xck + m * 16 + sp * 4);
            ull xb0 = bc2(xv.x), xb1 = bc2(xv.y), xb2 = bc2(xv.z), xb3 = bc2(xv.w);
#pragma unroll
            for (int j2 = 0; j2 < 8; ++j2) {
                ull wkv = wkg[j2 * 9 + m];
                kq[j2][0] = fma2(wkv, xb0, kq[j2][0]);
                kq[j2][1] = fma2(wkv, xb1, kq[j2][1]);
                kq[j2][2] = fma2(wkv, xb2, kq[j2][2]);
                kq[j2][3] = fma2(wkv, xb3, kq[j2][3]);
                ull wvv = wvg[j2 * 9 + m];
                vq[j2][0] = fma2(wvv, xb0, vq[j2][0]);
                vq[j2][1] = fma2(wvv, xb1, vq[j2][1]);
                vq[j2][2] = fma2(wvv, xb2, vq[j2][2]);
                vq[j2][3] = fma2(wvv, xb3, vq[j2][3]);
            }
        }
    }
    __syncthreads();   // qs/res complete before main loop

    const float* qso  = qs + o * 16 + sp * 4;
    const ull*   resp = reinterpret_cast<const ull*>(res) + sp * 2;
    float* op = out + ((b * 16) * 64 + o) * 4096 + hh0 * 64 + ww0 + 2 * sp;

#pragma unroll 1
    for (int i = 0; i < 16; ++i) {
        float4 qv = *reinterpret_cast<const float4*>(qso + i * QS_I);
        ull qb0 = bc2(qv.x), qb1 = bc2(qv.y), qb2 = bc2(qv.z), qb3 = bc2(qv.w);

        // att (pre-scaled) -> e = 2^att packed over j-pairs
        ull ep[8];
#pragma unroll
        for (int j2 = 0; j2 < 8; ++j2) {
            ull at = mul2(qb0, kq[j2][0]);
            at = fma2(qb1, kq[j2][1], at);
            at = fma2(qb2, kq[j2][2], at);
            at = fma2(qb3, kq[j2][3], at);
            float alo, ahi; upk2(at, alo, ahi);
            ep[j2] = pk2(ex2a(alo), ex2a(ahi));
        }

        // softmax denominator (packed tree + 1 horizontal)
        ull s = add2(add2(add2(ep[0], ep[1]), add2(ep[2], ep[3])),
                     add2(add2(ep[4], ep[5]), add2(ep[6], ep[7])));
        float slo, shi; upk2(s, slo, shi);
        ull invb = bc2(rcpa(slo + shi));

        // out[p] = horiz( sum_j2 ep[j2] (x) vq[j2][p] )  — no broadcasts needed
        ull a0 = mul2(ep[0], vq[0][0]);
        ull a1 = mul2(ep[0], vq[0][1]);
        ull a2 = mul2(ep[0], vq[0][2]);
        ull a3 = mul2(ep[0], vq[0][3]);
#pragma unroll
        for (int j2 = 1; j2 < 8; ++j2) {
            a0 = fma2(ep[j2], vq[j2][0], a0);
            a1 = fma2(ep[j2], vq[j2][1], a1);
            a2 = fma2(ep[j2], vq[j2][2], a2);
            a3 = fma2(ep[j2], vq[j2][3], a3);
        }
        float e0, e1, e2, e3, d0, d1, d2, d3;
        upk2(a0, e0, d0); upk2(a1, e1, d1);
        upk2(a2, e2, d2); upk2(a3, e3, d3);

        ull f0 = fma2(pk2(e0 + d0, e1 + d1), invb, resp[i * 8]);      // row hh0
        ull f1 = fma2(pk2(e2 + d2, e3 + d3), invb, resp[i * 8 + 1]);  // row hh0+1
        *reinterpret_cast<ull*>(op)      = f0;
        *reinterpret_cast<ull*>(op + 64) = f1;
        op += 64 * 4096;
    }
}

extern "C" void kernel_launch(void* const* d_in, const int* in_sizes, int n_in,
                              void* d_out, int out_size) {
    const float* x  = (const float*)d_in[0];
    const float* wq = (const float*)d_in[1];
    const float* wk = (const float*)d_in[2];
    const float* wv = (const float*)d_in[3];
    // d_in[4] (w_p): positional term is constant over the softmax axis -> cancels exactly.
    static int attr_set = 0;
    if (!attr_set) {
        cudaFuncSetAttribute(adapt_attn, cudaFuncAttributeMaxDynamicSharedMemorySize,
                             SMEM_BYTES);
        attr_set = 1;
    }
    dim3 grid(8, 32, 4);
    adapt_attn<<<grid, 256, SMEM_BYTES>>>(x, wq, wk, wv, (float*)d_out);
}